// round 3
// baseline (speedup 1.0000x reference)
#include <cuda_runtime.h>
#include <cstdint>

// Fused: out = swish(mult_w * swish(groupnorm(x @ W^T + b)))
// x:[4096,2048] W:[8192,2048] -> out:[4096,8192], 16 groups of 512 features.
//
// Portable-PTX version (ptxas target here is plain sm_103: NO tcgen05/TMA-a features).
// - mma.sync.aligned.m16n8k8 tf32 (legacy HMMA), register accumulators
// - CTA tile 128x256 (half a group), 256 threads, warp grid 2M x 4N (warp tile 64x64)
// - cluster of 2 CTAs covers one full group; per-row stats exchanged via DSMEM
// - cp.async 3-stage pipeline, smem rows padded to 36 floats (conflict-free LDS)

static constexpr int K_DIM  = 2048;
static constexpr int N_DIM  = 8192;
static constexpr int M_DIM  = 4096;
static constexpr int TILE_M = 128;
static constexpr int TILE_N = 256;
static constexpr int KC     = 32;
static constexpr int KTILES = K_DIM / KC;      // 64
static constexpr int THREADS = 256;
static constexpr int GRID = (M_DIM / TILE_M) * (N_DIM / TILE_N); // 32 * 32 = 1024

static constexpr int ROWF   = 36;              // padded row stride in floats
static constexpr int ROWB   = ROWF * 4;        // 144 bytes
static constexpr int A_BYTES = TILE_M * ROWB;              // 18432
static constexpr int B_BYTES = TILE_N * ROWB;              // 36864
static constexpr int STAGE_BYTES = A_BYTES + B_BYTES;      // 55296
static constexpr int NSTAGES = 3;

static constexpr int SM_PARAM = NSTAGES * STAGE_BYTES;        // 165888
static constexpr int SM_RED   = SM_PARAM + 4 * TILE_N * 4;    // 169984 (sum[128], sumsq[128])
static constexpr int SM_STATS = SM_RED + 2 * TILE_M * 4;      // 171008 (mean[128], rstd[128])
static constexpr int SMEM_TOTAL = SM_STATS + 2 * TILE_M * 4;  // 172032

#define DEVFN __device__ __forceinline__

DEVFN uint32_t s2u(const void* p) {
    uint32_t a;
    asm("{ .reg .u64 t; cvta.to.shared.u64 t, %1; cvt.u32.u64 %0, t; }" : "=r"(a) : "l"(p));
    return a;
}

DEVFN uint32_t f2tf32(float f) {
    uint32_t u;
    asm("cvt.rna.tf32.f32 %0, %1;" : "=r"(u) : "f"(f));
    return u;
}

DEVFN void mma_tf32(float c[4], const uint32_t a[4], const uint32_t b[2]) {
    asm volatile(
        "mma.sync.aligned.m16n8k8.row.col.f32.tf32.tf32.f32 "
        "{%0,%1,%2,%3}, {%4,%5,%6,%7}, {%8,%9}, {%0,%1,%2,%3};"
        : "+f"(c[0]), "+f"(c[1]), "+f"(c[2]), "+f"(c[3])
        : "r"(a[0]), "r"(a[1]), "r"(a[2]), "r"(a[3]), "r"(b[0]), "r"(b[1]));
}

DEVFN void cp16(uint32_t dst, const void* src) {
    asm volatile("cp.async.cg.shared.global [%0], [%1], 16;" :: "r"(dst), "l"(src));
}

__global__ void __launch_bounds__(THREADS, 1) __cluster_dims__(2, 1, 1)
fused_gemm_gn_silu(const float* __restrict__ x, const float* __restrict__ W,
                   const float* __restrict__ b, const float* __restrict__ gnw,
                   const float* __restrict__ gnb, const float* __restrict__ mw,
                   float* __restrict__ out)
{
    extern __shared__ char smem[];
    const uint32_t sb = s2u(smem);
    const int tid  = threadIdx.x;
    const int wid  = tid >> 5, lane = tid & 31;
    const int gid  = lane >> 2, ctid = lane & 3;
    const int wm   = wid & 1;        // 0..1 : 64-row band
    const int wn   = wid >> 1;       // 0..3 : 64-col band

    const int bx   = blockIdx.x;
    const int half = bx & 1;                 // cluster rank
    const int bm   = (bx >> 1) & 31;         // M block
    const int g    = bx >> 6;                // group 0..15
    const int nbase = g * 512 + half * TILE_N;

    // epilogue params
    float* bias_s = (float*)(smem + SM_PARAM);
    float* gnw_s  = bias_s + TILE_N;
    float* gnb_s  = gnw_s + TILE_N;
    float* mw_s   = gnb_s + TILE_N;
    float* red_s  = (float*)(smem + SM_RED);     // [0..127]=sum, [128..255]=sumsq
    float* mean_s = (float*)(smem + SM_STATS);   // [0..127]
    float* rstd_s = mean_s + TILE_M;

    bias_s[tid] = b[nbase + tid];
    gnw_s[tid]  = gnw[nbase + tid];
    gnb_s[tid]  = gnb[nbase + tid];
    mw_s[tid]   = mw[nbase + tid];
    red_s[tid]  = 0.f;

    const float* Abase = x + (size_t)bm * TILE_M * K_DIM;
    const float* Bbase = W + (size_t)nbase * K_DIM;

    auto load_stage = [&](int kt, int slot) {
        const int k0 = kt * KC;
        const uint32_t abuf = sb + slot * STAGE_BYTES;
        const uint32_t bbuf = abuf + A_BYTES;
#pragma unroll
        for (int i = 0; i < 4; i++) {          // A: 128 rows x 8 chunks
            int ch = tid + i * THREADS;
            int r = ch >> 3, j = ch & 7;
            cp16(abuf + r * ROWB + j * 16, Abase + (size_t)r * K_DIM + k0 + j * 4);
        }
#pragma unroll
        for (int i = 0; i < 8; i++) {          // B: 256 rows x 8 chunks
            int ch = tid + i * THREADS;
            int r = ch >> 3, j = ch & 7;
            cp16(bbuf + r * ROWB + j * 16, Bbase + (size_t)r * K_DIM + k0 + j * 4);
        }
        asm volatile("cp.async.commit_group;" ::: "memory");
    };

    float acc[4][8][4];
#pragma unroll
    for (int i = 0; i < 4; i++)
#pragma unroll
        for (int j = 0; j < 8; j++)
#pragma unroll
            for (int r = 0; r < 4; r++) acc[i][j][r] = 0.f;

    load_stage(0, 0);
    load_stage(1, 1);

    for (int t = 0; t < KTILES; t++) {
        asm volatile("cp.async.wait_group 1;" ::: "memory");
        __syncthreads();
        if (t + 2 < KTILES) load_stage(t + 2, (t + 2) % NSTAGES);

        const float* As = (const float*)(smem + (t % NSTAGES) * STAGE_BYTES);
        const float* Bs = (const float*)(smem + (t % NSTAGES) * STAGE_BYTES + A_BYTES);

#pragma unroll
        for (int ks = 0; ks < 4; ks++) {
            uint32_t afr[4][4];
#pragma unroll
            for (int i = 0; i < 4; i++) {
                const int row0 = wm * 64 + i * 16 + gid;
                const int kcol = ks * 8 + ctid;
                afr[i][0] = f2tf32(As[row0 * ROWF + kcol]);
                afr[i][1] = f2tf32(As[(row0 + 8) * ROWF + kcol]);
                afr[i][2] = f2tf32(As[row0 * ROWF + kcol + 4]);
                afr[i][3] = f2tf32(As[(row0 + 8) * ROWF + kcol + 4]);
            }
            uint32_t bfr[8][2];
#pragma unroll
            for (int j = 0; j < 8; j++) {
                const int nrow = wn * 64 + j * 8 + gid;
                const int kcol = ks * 8 + ctid;
                bfr[j][0] = f2tf32(Bs[nrow * ROWF + kcol]);
                bfr[j][1] = f2tf32(Bs[nrow * ROWF + kcol + 4]);
            }
#pragma unroll
            for (int i = 0; i < 4; i++)
#pragma unroll
                for (int j = 0; j < 8; j++)
                    mma_tf32(acc[i][j], afr[i], bfr[j]);
        }
    }
    asm volatile("cp.async.wait_group 0;" ::: "memory");
    __syncthreads();   // red_s zeroing + everyone past mainloop

    // ---- bias add + per-thread partial stats ----
    // acc[i][j]: c0,c1 -> row r0 = wm*64+16i+gid, cols nc, nc+1; c2,c3 -> row r0+8
    // nc = wn*64 + 8j + 2*ctid
    float psum0[4], psq0[4], psum1[4], psq1[4];
#pragma unroll
    for (int i = 0; i < 4; i++) { psum0[i] = psq0[i] = psum1[i] = psq1[i] = 0.f; }
#pragma unroll
    for (int i = 0; i < 4; i++) {
#pragma unroll
        for (int j = 0; j < 8; j++) {
            const int nc = wn * 64 + j * 8 + 2 * ctid;
            float y0 = acc[i][j][0] + bias_s[nc];
            float y1 = acc[i][j][1] + bias_s[nc + 1];
            float y2 = acc[i][j][2] + bias_s[nc];
            float y3 = acc[i][j][3] + bias_s[nc + 1];
            acc[i][j][0] = y0; acc[i][j][1] = y1; acc[i][j][2] = y2; acc[i][j][3] = y3;
            psum0[i] += y0 + y1;  psq0[i] += y0 * y0 + y1 * y1;
            psum1[i] += y2 + y3;  psq1[i] += y2 * y2 + y3 * y3;
        }
    }
    // quad reduce (ctid lanes share a row), then shared atomics
#pragma unroll
    for (int i = 0; i < 4; i++) {
#pragma unroll
        for (int d = 1; d < 4; d <<= 1) {
            psum0[i] += __shfl_xor_sync(0xffffffffu, psum0[i], d);
            psq0[i]  += __shfl_xor_sync(0xffffffffu, psq0[i], d);
            psum1[i] += __shfl_xor_sync(0xffffffffu, psum1[i], d);
            psq1[i]  += __shfl_xor_sync(0xffffffffu, psq1[i], d);
        }
        if (ctid == 0) {
            const int r0 = wm * 64 + i * 16 + gid;
            atomicAdd(&red_s[r0], psum0[i]);
            atomicAdd(&red_s[TILE_M + r0], psq0[i]);
            atomicAdd(&red_s[r0 + 8], psum1[i]);
            atomicAdd(&red_s[TILE_M + r0 + 8], psq1[i]);
        }
    }
    __syncthreads();

    // ---- cluster exchange of per-row partials ----
    uint32_t myrank;
    asm("mov.u32 %0, %%cluster_ctarank;" : "=r"(myrank));
    const uint32_t peer = myrank ^ 1u;

    asm volatile("barrier.cluster.arrive.aligned;" ::: "memory");
    asm volatile("barrier.cluster.wait.aligned;" ::: "memory");

    if (tid < TILE_M) {
        const uint32_t lsum = sb + SM_RED + tid * 4;
        const uint32_t lsq  = lsum + TILE_M * 4;
        uint32_t rsum, rsq;
        asm("mapa.shared::cluster.u32 %0, %1, %2;" : "=r"(rsum) : "r"(lsum), "r"(peer));
        asm("mapa.shared::cluster.u32 %0, %1, %2;" : "=r"(rsq)  : "r"(lsq),  "r"(peer));
        float ps, pq;
        asm volatile("ld.shared::cluster.f32 %0, [%1];" : "=f"(ps) : "r"(rsum));
        asm volatile("ld.shared::cluster.f32 %0, [%1];" : "=f"(pq) : "r"(rsq));
        const float s  = red_s[tid] + ps;
        const float sq = red_s[TILE_M + tid] + pq;
        const float mean = s * (1.0f / 512.0f);
        const float var  = fmaxf(sq * (1.0f / 512.0f) - mean * mean, 0.f);
        mean_s[tid] = mean;
        rstd_s[tid] = rsqrtf(var + 1e-5f);
    }
    __syncthreads();
    // peer may still be reading our red_s; arrive now, wait before exit
    asm volatile("barrier.cluster.arrive.aligned;" ::: "memory");

    // ---- normalize + SiLU chain + store ----
    float* obase = out + (size_t)(bm * TILE_M) * N_DIM + nbase;
#pragma unroll
    for (int i = 0; i < 4; i++) {
        const int r0 = wm * 64 + i * 16 + gid;
        const float m0 = mean_s[r0],     rs0 = rstd_s[r0];
        const float m1 = mean_s[r0 + 8], rs1 = rstd_s[r0 + 8];
#pragma unroll
        for (int j = 0; j < 8; j++) {
            const int nc = wn * 64 + j * 8 + 2 * ctid;
            const float gw0 = gnw_s[nc], gw1 = gnw_s[nc + 1];
            const float gb0 = gnb_s[nc], gb1 = gnb_s[nc + 1];
            const float w0  = mw_s[nc],  w1  = mw_s[nc + 1];
            float v[4];
            {
                float t0 = (acc[i][j][0] - m0) * rs0 * gw0 + gb0;
                float t1 = (acc[i][j][1] - m0) * rs0 * gw1 + gb1;
                float t2 = (acc[i][j][2] - m1) * rs1 * gw0 + gb0;
                float t3 = (acc[i][j][3] - m1) * rs1 * gw1 + gb1;
                float s0 = t0 / (1.f + __expf(-t0)) * w0;
                float s1 = t1 / (1.f + __expf(-t1)) * w1;
                float s2 = t2 / (1.f + __expf(-t2)) * w0;
                float s3 = t3 / (1.f + __expf(-t3)) * w1;
                v[0] = s0 / (1.f + __expf(-s0));
                v[1] = s1 / (1.f + __expf(-s1));
                v[2] = s2 / (1.f + __expf(-s2));
                v[3] = s3 / (1.f + __expf(-s3));
            }
            float2* p0 = (float2*)(obase + (size_t)r0 * N_DIM + nc);
            float2* p1 = (float2*)(obase + (size_t)(r0 + 8) * N_DIM + nc);
            *p0 = make_float2(v[0], v[1]);
            *p1 = make_float2(v[2], v[3]);
        }
    }

    asm volatile("barrier.cluster.wait.aligned;" ::: "memory");
}

extern "C" void kernel_launch(void* const* d_in, const int* in_sizes, int n_in,
                              void* d_out, int out_size)
{
    const float* x   = (const float*)d_in[0];
    const float* W   = (const float*)d_in[1];
    const float* b   = (const float*)d_in[2];
    const float* gnw = (const float*)d_in[3];
    const float* gnb = (const float*)d_in[4];
    const float* mw  = (const float*)d_in[5];
    float* out = (float*)d_out;

    cudaFuncSetAttribute(fused_gemm_gn_silu,
                         cudaFuncAttributeMaxDynamicSharedMemorySize, SMEM_TOTAL);
    fused_gemm_gn_silu<<<GRID, THREADS, SMEM_TOTAL>>>(x, W, b, gnw, gnb, mw, out);
}

// round 6
// speedup vs baseline: 1.1046x; 1.1046x over previous
#include <cuda_runtime.h>
#include <cstdint>

// Fused: out = swish(mult_w * swish(groupnorm(x @ W^T + b)))
// x:[4096,2048] W:[8192,2048] -> out:[4096,8192], 16 groups of 512 features.
//
// Portable-PTX (plain sm_103 ptxas target: no tcgen05).
// R6 == R4 resubmit (R5 was an infra failure; kernel never ran):
// - mainloop de-bloated: ldmatrix.x4 fragment loads (32/tile vs 128 scalar LDS)
// - no cvt.rna.tf32 (HW-truncated fp32 -> tf32; GroupNorm cancels the scale bias)
// - mma.sync.aligned.m16n8k8 tf32, register accumulators
// - CTA tile 128x256 (half group), 256 threads, warp tile 64x64
// - cluster of 2 CTAs = one group; row stats exchanged via DSMEM
// - cp.async 3-stage pipeline, smem row stride 36 floats (ldmatrix conflict-free)

static constexpr int K_DIM  = 2048;
static constexpr int N_DIM  = 8192;
static constexpr int M_DIM  = 4096;
static constexpr int TILE_M = 128;
static constexpr int TILE_N = 256;
static constexpr int KC     = 32;
static constexpr int KTILES = K_DIM / KC;      // 64
static constexpr int THREADS = 256;
static constexpr int GRID = (M_DIM / TILE_M) * (N_DIM / TILE_N); // 1024

static constexpr int ROWF   = 36;              // padded row stride in floats
static constexpr int ROWB   = ROWF * 4;        // 144 bytes
static constexpr int A_BYTES = TILE_M * ROWB;              // 18432
static constexpr int B_BYTES = TILE_N * ROWB;              // 36864
static constexpr int STAGE_BYTES = A_BYTES + B_BYTES;      // 55296
static constexpr int NSTAGES = 3;

static constexpr int SM_PARAM = NSTAGES * STAGE_BYTES;        // 165888
static constexpr int SM_RED   = SM_PARAM + 4 * TILE_N * 4;    // 169984
static constexpr int SM_STATS = SM_RED + 2 * TILE_M * 4;      // 171008
static constexpr int SMEM_TOTAL = SM_STATS + 2 * TILE_M * 4;  // 172032

#define DEVFN __device__ __forceinline__

DEVFN uint32_t s2u(const void* p) {
    uint32_t a;
    asm("{ .reg .u64 t; cvta.to.shared.u64 t, %1; cvt.u32.u64 %0, t; }" : "=r"(a) : "l"(p));
    return a;
}

DEVFN void mma_tf32(float c[4], const uint32_t a[4], const uint32_t b[2]) {
    asm volatile(
        "mma.sync.aligned.m16n8k8.row.col.f32.tf32.tf32.f32 "
        "{%0,%1,%2,%3}, {%4,%5,%6,%7}, {%8,%9}, {%0,%1,%2,%3};"
        : "+f"(c[0]), "+f"(c[1]), "+f"(c[2]), "+f"(c[3])
        : "r"(a[0]), "r"(a[1]), "r"(a[2]), "r"(a[3]), "r"(b[0]), "r"(b[1]));
}

DEVFN void ldsm4(uint32_t r[4], uint32_t addr) {
    asm volatile(
        "ldmatrix.sync.aligned.m8n8.x4.shared.b16 {%0,%1,%2,%3}, [%4];"
        : "=r"(r[0]), "=r"(r[1]), "=r"(r[2]), "=r"(r[3]) : "r"(addr));
}

DEVFN void cp16(uint32_t dst, const void* src) {
    asm volatile("cp.async.cg.shared.global [%0], [%1], 16;" :: "r"(dst), "l"(src));
}

__global__ void __launch_bounds__(THREADS, 1) __cluster_dims__(2, 1, 1)
fused_gemm_gn_silu(const float* __restrict__ x, const float* __restrict__ W,
                   const float* __restrict__ b, const float* __restrict__ gnw,
                   const float* __restrict__ gnb, const float* __restrict__ mw,
                   float* __restrict__ out)
{
    extern __shared__ char smem[];
    const uint32_t sb = s2u(smem);
    const int tid  = threadIdx.x;
    const int wid  = tid >> 5, lane = tid & 31;
    const int gid  = lane >> 2, ctid = lane & 3;
    const int wm   = wid & 1;        // 0..1 : 64-row band
    const int wn   = wid >> 1;       // 0..3 : 64-col band

    const int bx   = blockIdx.x;
    const int half = bx & 1;                 // cluster rank
    const int bm   = (bx >> 1) & 31;         // M block
    const int g    = bx >> 6;                // group 0..15
    const int nbase = g * 512 + half * TILE_N;

    // epilogue params
    float* bias_s = (float*)(smem + SM_PARAM);
    float* gnw_s  = bias_s + TILE_N;
    float* gnb_s  = gnw_s + TILE_N;
    float* mw_s   = gnb_s + TILE_N;
    float* red_s  = (float*)(smem + SM_RED);
    float* mean_s = (float*)(smem + SM_STATS);
    float* rstd_s = mean_s + TILE_M;

    bias_s[tid] = b[nbase + tid];
    gnw_s[tid]  = gnw[nbase + tid];
    gnb_s[tid]  = gnb[nbase + tid];
    mw_s[tid]   = mw[nbase + tid];
    red_s[tid]  = 0.f;

    const float* Abase = x + (size_t)bm * TILE_M * K_DIM;
    const float* Bbase = W + (size_t)nbase * K_DIM;

    auto load_stage = [&](int kt, int slot) {
        const int k0 = kt * KC;
        const uint32_t abuf = sb + slot * STAGE_BYTES;
        const uint32_t bbuf = abuf + A_BYTES;
#pragma unroll
        for (int i = 0; i < 4; i++) {
            int ch = tid + i * THREADS;
            int r = ch >> 3, j = ch & 7;
            cp16(abuf + r * ROWB + j * 16, Abase + (size_t)r * K_DIM + k0 + j * 4);
        }
#pragma unroll
        for (int i = 0; i < 8; i++) {
            int ch = tid + i * THREADS;
            int r = ch >> 3, j = ch & 7;
            cp16(bbuf + r * ROWB + j * 16, Bbase + (size_t)r * K_DIM + k0 + j * 4);
        }
        asm volatile("cp.async.commit_group;" ::: "memory");
    };

    // ldmatrix per-lane offsets
    // A x4: m0=(rows 0..7,klo) m1=(rows 8..15,klo) m2=(rows 0..7,khi) m3=(rows 8..15,khi)
    const int lq = lane >> 3, lr = lane & 7;
    const uint32_t a_lane = (uint32_t)((((lq & 1) * 8 + lr) * ROWB) + (lq >> 1) * 16);
    // B x4: m0=(n 0..7,klo) m1=(n 0..7,khi) m2=(n 8..15,klo) m3=(n 8..15,khi)
    const uint32_t b_lane = (uint32_t)((((lq >> 1) * 8 + lr) * ROWB) + (lq & 1) * 16);
    const uint32_t a_warp = (uint32_t)(wm * 64 * ROWB) + a_lane;
    const uint32_t b_warp = (uint32_t)(A_BYTES + wn * 64 * ROWB) + b_lane;

    float acc[4][8][4];
#pragma unroll
    for (int i = 0; i < 4; i++)
#pragma unroll
        for (int j = 0; j < 8; j++)
#pragma unroll
            for (int r = 0; r < 4; r++) acc[i][j][r] = 0.f;

    load_stage(0, 0);
    load_stage(1, 1);

    for (int t = 0; t < KTILES; t++) {
        asm volatile("cp.async.wait_group 1;" ::: "memory");
        __syncthreads();
        if (t + 2 < KTILES) load_stage(t + 2, (t + 2) % NSTAGES);

        const uint32_t stage = sb + (t % NSTAGES) * STAGE_BYTES;
        const uint32_t aaddr = stage + a_warp;
        const uint32_t baddr = stage + b_warp;

#pragma unroll
        for (int ks = 0; ks < 4; ks++) {
            uint32_t afr[4][4];
#pragma unroll
            for (int i = 0; i < 4; i++)
                ldsm4(afr[i], aaddr + i * 16 * ROWB + ks * 32);
            uint32_t bfr[4][4];
#pragma unroll
            for (int jp = 0; jp < 4; jp++)
                ldsm4(bfr[jp], baddr + jp * 16 * ROWB + ks * 32);
#pragma unroll
            for (int i = 0; i < 4; i++)
#pragma unroll
                for (int j = 0; j < 8; j++)
                    mma_tf32(acc[i][j], afr[i], &bfr[j >> 1][(j & 1) * 2]);
        }
    }
    asm volatile("cp.async.wait_group 0;" ::: "memory");
    __syncthreads();

    // ---- bias add + per-thread partial stats ----
    float psum0[4], psq0[4], psum1[4], psq1[4];
#pragma unroll
    for (int i = 0; i < 4; i++) { psum0[i] = psq0[i] = psum1[i] = psq1[i] = 0.f; }
#pragma unroll
    for (int i = 0; i < 4; i++) {
#pragma unroll
        for (int j = 0; j < 8; j++) {
            const int nc = wn * 64 + j * 8 + 2 * ctid;
            float y0 = acc[i][j][0] + bias_s[nc];
            float y1 = acc[i][j][1] + bias_s[nc + 1];
            float y2 = acc[i][j][2] + bias_s[nc];
            float y3 = acc[i][j][3] + bias_s[nc + 1];
            acc[i][j][0] = y0; acc[i][j][1] = y1; acc[i][j][2] = y2; acc[i][j][3] = y3;
            psum0[i] += y0 + y1;  psq0[i] += y0 * y0 + y1 * y1;
            psum1[i] += y2 + y3;  psq1[i] += y2 * y2 + y3 * y3;
        }
    }
#pragma unroll
    for (int i = 0; i < 4; i++) {
#pragma unroll
        for (int d = 1; d < 4; d <<= 1) {
            psum0[i] += __shfl_xor_sync(0xffffffffu, psum0[i], d);
            psq0[i]  += __shfl_xor_sync(0xffffffffu, psq0[i], d);
            psum1[i] += __shfl_xor_sync(0xffffffffu, psum1[i], d);
            psq1[i]  += __shfl_xor_sync(0xffffffffu, psq1[i], d);
        }
        if (ctid == 0) {
            const int r0 = wm * 64 + i * 16 + gid;
            atomicAdd(&red_s[r0], psum0[i]);
            atomicAdd(&red_s[TILE_M + r0], psq0[i]);
            atomicAdd(&red_s[r0 + 8], psum1[i]);
            atomicAdd(&red_s[TILE_M + r0 + 8], psq1[i]);
        }
    }
    __syncthreads();

    // ---- cluster exchange of per-row partials ----
    uint32_t myrank;
    asm("mov.u32 %0, %%cluster_ctarank;" : "=r"(myrank));
    const uint32_t peer = myrank ^ 1u;

    asm volatile("barrier.cluster.arrive.aligned;" ::: "memory");
    asm volatile("barrier.cluster.wait.aligned;" ::: "memory");

    if (tid < TILE_M) {
        const uint32_t lsum = sb + SM_RED + tid * 4;
        const uint32_t lsq  = lsum + TILE_M * 4;
        uint32_t rsum, rsq;
        asm("mapa.shared::cluster.u32 %0, %1, %2;" : "=r"(rsum) : "r"(lsum), "r"(peer));
        asm("mapa.shared::cluster.u32 %0, %1, %2;" : "=r"(rsq)  : "r"(lsq),  "r"(peer));
        float ps, pq;
        asm volatile("ld.shared::cluster.f32 %0, [%1];" : "=f"(ps) : "r"(rsum));
        asm volatile("ld.shared::cluster.f32 %0, [%1];" : "=f"(pq) : "r"(rsq));
        const float s  = red_s[tid] + ps;
        const float sq = red_s[TILE_M + tid] + pq;
        const float mean = s * (1.0f / 512.0f);
        const float var  = fmaxf(sq * (1.0f / 512.0f) - mean * mean, 0.f);
        mean_s[tid] = mean;
        rstd_s[tid] = rsqrtf(var + 1e-5f);
    }
    __syncthreads();
    asm volatile("barrier.cluster.arrive.aligned;" ::: "memory");

    // ---- normalize + SiLU chain + store ----
    float* obase = out + (size_t)(bm * TILE_M) * N_DIM + nbase;
#pragma unroll
    for (int i = 0; i < 4; i++) {
        const int r0 = wm * 64 + i * 16 + gid;
        const float m0 = mean_s[r0],     rs0 = rstd_s[r0];
        const float m1 = mean_s[r0 + 8], rs1 = rstd_s[r0 + 8];
#pragma unroll
        for (int j = 0; j < 8; j++) {
            const int nc = wn * 64 + j * 8 + 2 * ctid;
            const float gw0 = gnw_s[nc], gw1 = gnw_s[nc + 1];
            const float gb0 = gnb_s[nc], gb1 = gnb_s[nc + 1];
            const float w0  = mw_s[nc],  w1  = mw_s[nc + 1];
            float v[4];
            {
                float t0 = (acc[i][j][0] - m0) * rs0 * gw0 + gb0;
                float t1 = (acc[i][j][1] - m0) * rs0 * gw1 + gb1;
                float t2 = (acc[i][j][2] - m1) * rs1 * gw0 + gb0;
                float t3 = (acc[i][j][3] - m1) * rs1 * gw1 + gb1;
                float s0 = t0 / (1.f + __expf(-t0)) * w0;
                float s1 = t1 / (1.f + __expf(-t1)) * w1;
                float s2 = t2 / (1.f + __expf(-t2)) * w0;
                float s3 = t3 / (1.f + __expf(-t3)) * w1;
                v[0] = s0 / (1.f + __expf(-s0));
                v[1] = s1 / (1.f + __expf(-s1));
                v[2] = s2 / (1.f + __expf(-s2));
                v[3] = s3 / (1.f + __expf(-s3));
            }
            float2* p0 = (float2*)(obase + (size_t)r0 * N_DIM + nc);
            float2* p1 = (float2*)(obase + (size_t)(r0 + 8) * N_DIM + nc);
            *p0 = make_float2(v[0], v[1]);
            *p1 = make_float2(v[2], v[3]);
        }
    }

    asm volatile("barrier.cluster.wait.aligned;" ::: "memory");
}

extern "C" void kernel_launch(void* const* d_in, const int* in_sizes, int n_in,
                              void* d_out, int out_size)
{
    const float* x   = (const float*)d_in[0];
    const float* W   = (const float*)d_in[1];
    const float* b   = (const float*)d_in[2];
    const float* gnw = (const float*)d_in[3];
    const float* gnb = (const float*)d_in[4];
    const float* mw  = (const float*)d_in[5];
    float* out = (float*)d_out;

    cudaFuncSetAttribute(fused_gemm_gn_silu,
                         cudaFuncAttributeMaxDynamicSharedMemorySize, SMEM_TOTAL);
    fused_gemm_gn_silu<<<GRID, THREADS, SMEM_TOTAL>>>(x, W, b, gnw, gnb, mw, out);
}

// round 7
// speedup vs baseline: 1.2044x; 1.0904x over previous
#include <cuda_runtime.h>
#include <cstdint>

// Fused: out = swish(mult_w * swish(groupnorm(x @ W^T + b)))
// x:[4096,2048] W:[8192,2048] -> out:[4096,8192], 16 groups of 512 features.
//
// Portable-PTX (plain sm_103 ptxas target: no tcgen05).
// R7: latency-hiding fix — 512 threads (16 warps, 4/SMSP), warp tile 32x64.
// R6 showed tensor=49.8% @ issue=16.5%: mainloop is RAW/barrier latency-bound
// with only 2 warps/SMSP; doubling resident warps converts stalls to overlap.
// - mma.sync.aligned.m16n8k8 tf32, register accumulators (64/thread)
// - ldmatrix.x4 fragment loads, no cvt (HW tf32 truncation; GN cancels bias)
// - CTA tile 128x256 (half group), cluster of 2 CTAs = one group (DSMEM stats)
// - cp.async 3-stage pipeline, smem row stride 36 floats (conflict-free)

static constexpr int K_DIM  = 2048;
static constexpr int N_DIM  = 8192;
static constexpr int M_DIM  = 4096;
static constexpr int TILE_M = 128;
static constexpr int TILE_N = 256;
static constexpr int KC     = 32;
static constexpr int KTILES = K_DIM / KC;      // 64
static constexpr int THREADS = 512;
static constexpr int GRID = (M_DIM / TILE_M) * (N_DIM / TILE_N); // 1024

static constexpr int ROWF   = 36;              // padded row stride in floats
static constexpr int ROWB   = ROWF * 4;        // 144 bytes
static constexpr int A_BYTES = TILE_M * ROWB;              // 18432
static constexpr int B_BYTES = TILE_N * ROWB;              // 36864
static constexpr int STAGE_BYTES = A_BYTES + B_BYTES;      // 55296
static constexpr int NSTAGES = 3;

static constexpr int SM_PARAM = NSTAGES * STAGE_BYTES;        // 165888
static constexpr int SM_RED   = SM_PARAM + 4 * TILE_N * 4;    // 169984
static constexpr int SM_STATS = SM_RED + 2 * TILE_M * 4;      // 171008
static constexpr int SMEM_TOTAL = SM_STATS + 2 * TILE_M * 4;  // 172032

#define DEVFN __device__ __forceinline__

DEVFN uint32_t s2u(const void* p) {
    uint32_t a;
    asm("{ .reg .u64 t; cvta.to.shared.u64 t, %1; cvt.u32.u64 %0, t; }" : "=r"(a) : "l"(p));
    return a;
}

DEVFN void mma_tf32(float c[4], const uint32_t a[4], const uint32_t b[2]) {
    asm volatile(
        "mma.sync.aligned.m16n8k8.row.col.f32.tf32.tf32.f32 "
        "{%0,%1,%2,%3}, {%4,%5,%6,%7}, {%8,%9}, {%0,%1,%2,%3};"
        : "+f"(c[0]), "+f"(c[1]), "+f"(c[2]), "+f"(c[3])
        : "r"(a[0]), "r"(a[1]), "r"(a[2]), "r"(a[3]), "r"(b[0]), "r"(b[1]));
}

DEVFN void ldsm4(uint32_t r[4], uint32_t addr) {
    asm volatile(
        "ldmatrix.sync.aligned.m8n8.x4.shared.b16 {%0,%1,%2,%3}, [%4];"
        : "=r"(r[0]), "=r"(r[1]), "=r"(r[2]), "=r"(r[3]) : "r"(addr));
}

DEVFN void cp16(uint32_t dst, const void* src) {
    asm volatile("cp.async.cg.shared.global [%0], [%1], 16;" :: "r"(dst), "l"(src));
}

__global__ void __launch_bounds__(THREADS, 1) __cluster_dims__(2, 1, 1)
fused_gemm_gn_silu(const float* __restrict__ x, const float* __restrict__ W,
                   const float* __restrict__ b, const float* __restrict__ gnw,
                   const float* __restrict__ gnb, const float* __restrict__ mw,
                   float* __restrict__ out)
{
    extern __shared__ char smem[];
    const uint32_t sb = s2u(smem);
    const int tid  = threadIdx.x;
    const int wid  = tid >> 5, lane = tid & 31;
    const int gid  = lane >> 2, ctid = lane & 3;
    const int wm   = wid & 3;        // 0..3 : 32-row band
    const int wn   = wid >> 2;       // 0..3 : 64-col band

    const int bx   = blockIdx.x;
    const int half = bx & 1;                 // cluster rank
    const int bm   = (bx >> 1) & 31;         // M block
    const int g    = bx >> 6;                // group 0..15
    const int nbase = g * 512 + half * TILE_N;

    // epilogue params
    float* bias_s = (float*)(smem + SM_PARAM);
    float* gnw_s  = bias_s + TILE_N;
    float* gnb_s  = gnw_s + TILE_N;
    float* mw_s   = gnb_s + TILE_N;
    float* red_s  = (float*)(smem + SM_RED);
    float* mean_s = (float*)(smem + SM_STATS);
    float* rstd_s = mean_s + TILE_M;

    if (tid < TILE_N) {
        bias_s[tid] = b[nbase + tid];
        gnw_s[tid]  = gnw[nbase + tid];
        gnb_s[tid]  = gnb[nbase + tid];
        mw_s[tid]   = mw[nbase + tid];
        red_s[tid]  = 0.f;
    }

    const float* Abase = x + (size_t)bm * TILE_M * K_DIM;
    const float* Bbase = W + (size_t)nbase * K_DIM;

    auto load_stage = [&](int kt, int slot) {
        const int k0 = kt * KC;
        const uint32_t abuf = sb + slot * STAGE_BYTES;
        const uint32_t bbuf = abuf + A_BYTES;
#pragma unroll
        for (int i = 0; i < 2; i++) {          // A: 128 rows x 8 chunks = 1024
            int ch = tid + i * THREADS;
            int r = ch >> 3, j = ch & 7;
            cp16(abuf + r * ROWB + j * 16, Abase + (size_t)r * K_DIM + k0 + j * 4);
        }
#pragma unroll
        for (int i = 0; i < 4; i++) {          // B: 256 rows x 8 chunks = 2048
            int ch = tid + i * THREADS;
            int r = ch >> 3, j = ch & 7;
            cp16(bbuf + r * ROWB + j * 16, Bbase + (size_t)r * K_DIM + k0 + j * 4);
        }
        asm volatile("cp.async.commit_group;" ::: "memory");
    };

    // ldmatrix per-lane offsets
    // A x4: m0=(rows 0..7,klo) m1=(rows 8..15,klo) m2=(rows 0..7,khi) m3=(rows 8..15,khi)
    const int lq = lane >> 3, lr = lane & 7;
    const uint32_t a_lane = (uint32_t)((((lq & 1) * 8 + lr) * ROWB) + (lq >> 1) * 16);
    // B x4: m0=(n 0..7,klo) m1=(n 0..7,khi) m2=(n 8..15,klo) m3=(n 8..15,khi)
    const uint32_t b_lane = (uint32_t)((((lq >> 1) * 8 + lr) * ROWB) + (lq & 1) * 16);
    const uint32_t a_warp = (uint32_t)(wm * 32 * ROWB) + a_lane;
    const uint32_t b_warp = (uint32_t)(A_BYTES + wn * 64 * ROWB) + b_lane;

    float acc[2][8][4];
#pragma unroll
    for (int i = 0; i < 2; i++)
#pragma unroll
        for (int j = 0; j < 8; j++)
#pragma unroll
            for (int r = 0; r < 4; r++) acc[i][j][r] = 0.f;

    load_stage(0, 0);
    load_stage(1, 1);

    for (int t = 0; t < KTILES; t++) {
        asm volatile("cp.async.wait_group 1;" ::: "memory");
        __syncthreads();
        if (t + 2 < KTILES) load_stage(t + 2, (t + 2) % NSTAGES);

        const uint32_t stage = sb + (t % NSTAGES) * STAGE_BYTES;
        const uint32_t aaddr = stage + a_warp;
        const uint32_t baddr = stage + b_warp;

#pragma unroll
        for (int ks = 0; ks < 4; ks++) {
            uint32_t afr[2][4];
#pragma unroll
            for (int i = 0; i < 2; i++)
                ldsm4(afr[i], aaddr + i * 16 * ROWB + ks * 32);
            uint32_t bfr[4][4];
#pragma unroll
            for (int jp = 0; jp < 4; jp++)
                ldsm4(bfr[jp], baddr + jp * 16 * ROWB + ks * 32);
#pragma unroll
            for (int i = 0; i < 2; i++)
#pragma unroll
                for (int j = 0; j < 8; j++)
                    mma_tf32(acc[i][j], afr[i], &bfr[j >> 1][(j & 1) * 2]);
        }
    }
    asm volatile("cp.async.wait_group 0;" ::: "memory");
    __syncthreads();

    // ---- bias add + per-thread partial stats ----
    float psum0[2], psq0[2], psum1[2], psq1[2];
#pragma unroll
    for (int i = 0; i < 2; i++) { psum0[i] = psq0[i] = psum1[i] = psq1[i] = 0.f; }
#pragma unroll
    for (int i = 0; i < 2; i++) {
#pragma unroll
        for (int j = 0; j < 8; j++) {
            const int nc = wn * 64 + j * 8 + 2 * ctid;
            float y0 = acc[i][j][0] + bias_s[nc];
            float y1 = acc[i][j][1] + bias_s[nc + 1];
            float y2 = acc[i][j][2] + bias_s[nc];
            float y3 = acc[i][j][3] + bias_s[nc + 1];
            acc[i][j][0] = y0; acc[i][j][1] = y1; acc[i][j][2] = y2; acc[i][j][3] = y3;
            psum0[i] += y0 + y1;  psq0[i] += y0 * y0 + y1 * y1;
            psum1[i] += y2 + y3;  psq1[i] += y2 * y2 + y3 * y3;
        }
    }
#pragma unroll
    for (int i = 0; i < 2; i++) {
#pragma unroll
        for (int d = 1; d < 4; d <<= 1) {
            psum0[i] += __shfl_xor_sync(0xffffffffu, psum0[i], d);
            psq0[i]  += __shfl_xor_sync(0xffffffffu, psq0[i], d);
            psum1[i] += __shfl_xor_sync(0xffffffffu, psum1[i], d);
            psq1[i]  += __shfl_xor_sync(0xffffffffu, psq1[i], d);
        }
        if (ctid == 0) {
            const int r0 = wm * 32 + i * 16 + gid;
            atomicAdd(&red_s[r0], psum0[i]);
            atomicAdd(&red_s[TILE_M + r0], psq0[i]);
            atomicAdd(&red_s[r0 + 8], psum1[i]);
            atomicAdd(&red_s[TILE_M + r0 + 8], psq1[i]);
        }
    }
    __syncthreads();

    // ---- cluster exchange of per-row partials ----
    uint32_t myrank;
    asm("mov.u32 %0, %%cluster_ctarank;" : "=r"(myrank));
    const uint32_t peer = myrank ^ 1u;

    asm volatile("barrier.cluster.arrive.aligned;" ::: "memory");
    asm volatile("barrier.cluster.wait.aligned;" ::: "memory");

    if (tid < TILE_M) {
        const uint32_t lsum = sb + SM_RED + tid * 4;
        const uint32_t lsq  = lsum + TILE_M * 4;
        uint32_t rsum, rsq;
        asm("mapa.shared::cluster.u32 %0, %1, %2;" : "=r"(rsum) : "r"(lsum), "r"(peer));
        asm("mapa.shared::cluster.u32 %0, %1, %2;" : "=r"(rsq)  : "r"(lsq),  "r"(peer));
        float ps, pq;
        asm volatile("ld.shared::cluster.f32 %0, [%1];" : "=f"(ps) : "r"(rsum));
        asm volatile("ld.shared::cluster.f32 %0, [%1];" : "=f"(pq) : "r"(rsq));
        const float s  = red_s[tid] + ps;
        const float sq = red_s[TILE_M + tid] + pq;
        const float mean = s * (1.0f / 512.0f);
        const float var  = fmaxf(sq * (1.0f / 512.0f) - mean * mean, 0.f);
        mean_s[tid] = mean;
        rstd_s[tid] = rsqrtf(var + 1e-5f);
    }
    __syncthreads();
    asm volatile("barrier.cluster.arrive.aligned;" ::: "memory");

    // ---- normalize + SiLU chain + store ----
    float* obase = out + (size_t)(bm * TILE_M) * N_DIM + nbase;
#pragma unroll
    for (int i = 0; i < 2; i++) {
        const int r0 = wm * 32 + i * 16 + gid;
        const float m0 = mean_s[r0],     rs0 = rstd_s[r0];
        const float m1 = mean_s[r0 + 8], rs1 = rstd_s[r0 + 8];
#pragma unroll
        for (int j = 0; j < 8; j++) {
            const int nc = wn * 64 + j * 8 + 2 * ctid;
            const float gw0 = gnw_s[nc], gw1 = gnw_s[nc + 1];
            const float gb0 = gnb_s[nc], gb1 = gnb_s[nc + 1];
            const float w0  = mw_s[nc],  w1  = mw_s[nc + 1];
            float v[4];
            {
                float t0 = (acc[i][j][0] - m0) * rs0 * gw0 + gb0;
                float t1 = (acc[i][j][1] - m0) * rs0 * gw1 + gb1;
                float t2 = (acc[i][j][2] - m1) * rs1 * gw0 + gb0;
                float t3 = (acc[i][j][3] - m1) * rs1 * gw1 + gb1;
                float s0 = t0 / (1.f + __expf(-t0)) * w0;
                float s1 = t1 / (1.f + __expf(-t1)) * w1;
                float s2 = t2 / (1.f + __expf(-t2)) * w0;
                float s3 = t3 / (1.f + __expf(-t3)) * w1;
                v[0] = s0 / (1.f + __expf(-s0));
                v[1] = s1 / (1.f + __expf(-s1));
                v[2] = s2 / (1.f + __expf(-s2));
                v[3] = s3 / (1.f + __expf(-s3));
            }
            float2* p0 = (float2*)(obase + (size_t)r0 * N_DIM + nc);
            float2* p1 = (float2*)(obase + (size_t)(r0 + 8) * N_DIM + nc);
            *p0 = make_float2(v[0], v[1]);
            *p1 = make_float2(v[2], v[3]);
        }
    }

    asm volatile("barrier.cluster.wait.aligned;" ::: "memory");
}

extern "C" void kernel_launch(void* const* d_in, const int* in_sizes, int n_in,
                              void* d_out, int out_size)
{
    const float* x   = (const float*)d_in[0];
    const float* W   = (const float*)d_in[1];
    const float* b   = (const float*)d_in[2];
    const float* gnw = (const float*)d_in[3];
    const float* gnb = (const float*)d_in[4];
    const float* mw  = (const float*)d_in[5];
    float* out = (float*)d_out;

    cudaFuncSetAttribute(fused_gemm_gn_silu,
                         cudaFuncAttributeMaxDynamicSharedMemorySize, SMEM_TOTAL);
    fused_gemm_gn_silu<<<GRID, THREADS, SMEM_TOTAL>>>(x, W, b, gnw, gnb, mw, out);
}

// round 8
// speedup vs baseline: 2.0679x; 1.7170x over previous
#include <cuda_runtime.h>
#include <cuda_fp16.h>
#include <cstdint>

// Fused: out = swish(mult_w * swish(groupnorm(x @ W^T + b)))
// x:[4096,2048] W:[8192,2048] -> out:[4096,8192], 16 groups of 512 features.
//
// R8: fp16 pivot. Tensor busy time was a constant ~448us across R3/R6/R7
// (tf32 m16n8k8 floor). fp16 m16n8k16 runs 2x rate with the SAME 10-bit
// mantissa (values are O(1); fp32 accum) -> floor ~225us.
// - pre-pass kernel converts x,W fp32 -> fp16 into __device__ scratch (~30us)
// - GEMM: KC=64 per stage (same stage bytes, half the k-tiles/barriers)
// - ldmatrix.x4 b16 fragment loads; identical lane formulas as tf32 version
// - CTA 128x256 (half group), 512 thr, warp tile 32x64, cluster-2 DSMEM stats
// - cp.async 3-stage pipeline, smem row stride 144B (conflict-free)

static constexpr int K_DIM  = 2048;
static constexpr int N_DIM  = 8192;
static constexpr int M_DIM  = 4096;
static constexpr int TILE_M = 128;
static constexpr int TILE_N = 256;
static constexpr int KC     = 64;              // fp16: 64 k per stage = 128B/row
static constexpr int KTILES = K_DIM / KC;      // 32
static constexpr int THREADS = 512;
static constexpr int GRID = (M_DIM / TILE_M) * (N_DIM / TILE_N); // 1024

static constexpr int ROWB   = 144;             // 128B data + 16B pad
static constexpr int A_BYTES = TILE_M * ROWB;              // 18432
static constexpr int B_BYTES = TILE_N * ROWB;              // 36864
static constexpr int STAGE_BYTES = A_BYTES + B_BYTES;      // 55296
static constexpr int NSTAGES = 3;

static constexpr int SM_PARAM = NSTAGES * STAGE_BYTES;        // 165888
static constexpr int SM_RED   = SM_PARAM + 4 * TILE_N * 4;    // 169984
static constexpr int SM_STATS = SM_RED + 2 * TILE_M * 4;      // 171008
static constexpr int SMEM_TOTAL = SM_STATS + 2 * TILE_M * 4;  // 172032

// fp16 scratch (static device globals: allowed; no dynamic allocation)
__device__ __half g_x16[(size_t)M_DIM * K_DIM];   // 16 MB
__device__ __half g_w16[(size_t)N_DIM * K_DIM];   // 32 MB

#define DEVFN __device__ __forceinline__

DEVFN uint32_t s2u(const void* p) {
    uint32_t a;
    asm("{ .reg .u64 t; cvta.to.shared.u64 t, %1; cvt.u32.u64 %0, t; }" : "=r"(a) : "l"(p));
    return a;
}

DEVFN void mma_f16(float c[4], const uint32_t a[4], const uint32_t b[2]) {
    asm volatile(
        "mma.sync.aligned.m16n8k16.row.col.f32.f16.f16.f32 "
        "{%0,%1,%2,%3}, {%4,%5,%6,%7}, {%8,%9}, {%0,%1,%2,%3};"
        : "+f"(c[0]), "+f"(c[1]), "+f"(c[2]), "+f"(c[3])
        : "r"(a[0]), "r"(a[1]), "r"(a[2]), "r"(a[3]), "r"(b[0]), "r"(b[1]));
}

DEVFN void ldsm4(uint32_t r[4], uint32_t addr) {
    asm volatile(
        "ldmatrix.sync.aligned.m8n8.x4.shared.b16 {%0,%1,%2,%3}, [%4];"
        : "=r"(r[0]), "=r"(r[1]), "=r"(r[2]), "=r"(r[3]) : "r"(addr));
}

DEVFN void cp16(uint32_t dst, const void* src) {
    asm volatile("cp.async.cg.shared.global [%0], [%1], 16;" :: "r"(dst), "l"(src));
}

// ---- pre-pass: fp32 -> fp16 for x and W ----
__global__ void __launch_bounds__(256)
convert_f32_to_f16(const float* __restrict__ x, const float* __restrict__ W)
{
    const size_t XN4 = (size_t)M_DIM * K_DIM / 4;
    const size_t WN4 = (size_t)N_DIM * K_DIM / 4;
    const size_t total = XN4 + WN4;
    const size_t stride = (size_t)gridDim.x * blockDim.x;
    for (size_t i = (size_t)blockIdx.x * blockDim.x + threadIdx.x; i < total; i += stride) {
        float4 v;
        __half2* dst;
        if (i < XN4) {
            v = ((const float4*)x)[i];
            dst = (__half2*)g_x16 + i * 2;
        } else {
            v = ((const float4*)W)[i - XN4];
            dst = (__half2*)g_w16 + (i - XN4) * 2;
        }
        dst[0] = __floats2half2_rn(v.x, v.y);
        dst[1] = __floats2half2_rn(v.z, v.w);
    }
}

__global__ void __launch_bounds__(THREADS, 1) __cluster_dims__(2, 1, 1)
fused_gemm_gn_silu(const float* __restrict__ b, const float* __restrict__ gnw,
                   const float* __restrict__ gnb, const float* __restrict__ mw,
                   float* __restrict__ out)
{
    extern __shared__ char smem[];
    const uint32_t sb = s2u(smem);
    const int tid  = threadIdx.x;
    const int wid  = tid >> 5, lane = tid & 31;
    const int gid  = lane >> 2, ctid = lane & 3;
    const int wm   = wid & 3;        // 0..3 : 32-row band
    const int wn   = wid >> 2;       // 0..3 : 64-col band

    const int bx   = blockIdx.x;
    const int half = bx & 1;                 // cluster rank
    const int bm   = (bx >> 1) & 31;         // M block
    const int g    = bx >> 6;                // group 0..15
    const int nbase = g * 512 + half * TILE_N;

    float* bias_s = (float*)(smem + SM_PARAM);
    float* gnw_s  = bias_s + TILE_N;
    float* gnb_s  = gnw_s + TILE_N;
    float* mw_s   = gnb_s + TILE_N;
    float* red_s  = (float*)(smem + SM_RED);
    float* mean_s = (float*)(smem + SM_STATS);
    float* rstd_s = mean_s + TILE_M;

    if (tid < TILE_N) {
        bias_s[tid] = b[nbase + tid];
        gnw_s[tid]  = gnw[nbase + tid];
        gnb_s[tid]  = gnb[nbase + tid];
        mw_s[tid]   = mw[nbase + tid];
        red_s[tid]  = 0.f;
    }

    const __half* Abase = g_x16 + (size_t)bm * TILE_M * K_DIM;
    const __half* Bbase = g_w16 + (size_t)nbase * K_DIM;

    // stage fill: rows of 128B (64 halves) in 16B chunks (8 per row)
    auto load_stage = [&](int kt, int slot) {
        const int k0 = kt * KC;
        const uint32_t abuf = sb + slot * STAGE_BYTES;
        const uint32_t bbuf = abuf + A_BYTES;
#pragma unroll
        for (int i = 0; i < 2; i++) {          // A: 128 rows x 8 chunks = 1024
            int ch = tid + i * THREADS;
            int r = ch >> 3, j = ch & 7;
            cp16(abuf + r * ROWB + j * 16, Abase + (size_t)r * K_DIM + k0 + j * 8);
        }
#pragma unroll
        for (int i = 0; i < 4; i++) {          // B: 256 rows x 8 chunks = 2048
            int ch = tid + i * THREADS;
            int r = ch >> 3, j = ch & 7;
            cp16(bbuf + r * ROWB + j * 16, Bbase + (size_t)r * K_DIM + k0 + j * 8);
        }
        asm volatile("cp.async.commit_group;" ::: "memory");
    };

    // ldmatrix lane offsets (b16 tiles, 16B per 8x8 tile row)
    // A x4: m0=(rows 0..7,klo16B) m1=(rows 8..15,klo) m2=(rows 0..7,khi) m3=(rows 8..15,khi)
    const int lq = lane >> 3, lr = lane & 7;
    const uint32_t a_lane = (uint32_t)((((lq & 1) * 8 + lr) * ROWB) + (lq >> 1) * 16);
    // B x4: m0=(n 0..7,klo) m1=(n 0..7,khi) m2=(n 8..15,klo) m3=(n 8..15,khi)
    const uint32_t b_lane = (uint32_t)((((lq >> 1) * 8 + lr) * ROWB) + (lq & 1) * 16);
    const uint32_t a_warp = (uint32_t)(wm * 32 * ROWB) + a_lane;
    const uint32_t b_warp = (uint32_t)(A_BYTES + wn * 64 * ROWB) + b_lane;

    float acc[2][8][4];
#pragma unroll
    for (int i = 0; i < 2; i++)
#pragma unroll
        for (int j = 0; j < 8; j++)
#pragma unroll
            for (int r = 0; r < 4; r++) acc[i][j][r] = 0.f;

    load_stage(0, 0);
    load_stage(1, 1);

    for (int t = 0; t < KTILES; t++) {
        asm volatile("cp.async.wait_group 1;" ::: "memory");
        __syncthreads();
        if (t + 2 < KTILES) load_stage(t + 2, (t + 2) % NSTAGES);

        const uint32_t stage = sb + (t % NSTAGES) * STAGE_BYTES;
        const uint32_t aaddr = stage + a_warp;
        const uint32_t baddr = stage + b_warp;

#pragma unroll
        for (int ks = 0; ks < 4; ks++) {       // 4 chunks of k16, 32B each
            uint32_t afr[2][4];
#pragma unroll
            for (int i = 0; i < 2; i++)
                ldsm4(afr[i], aaddr + i * 16 * ROWB + ks * 32);
            uint32_t bfr[4][4];
#pragma unroll
            for (int jp = 0; jp < 4; jp++)
                ldsm4(bfr[jp], baddr + jp * 16 * ROWB + ks * 32);
#pragma unroll
            for (int i = 0; i < 2; i++)
#pragma unroll
                for (int j = 0; j < 8; j++)
                    mma_f16(acc[i][j], afr[i], &bfr[j >> 1][(j & 1) * 2]);
        }
    }
    asm volatile("cp.async.wait_group 0;" ::: "memory");
    __syncthreads();

    // ---- bias add + per-thread partial stats ----
    float psum0[2], psq0[2], psum1[2], psq1[2];
#pragma unroll
    for (int i = 0; i < 2; i++) { psum0[i] = psq0[i] = psum1[i] = psq1[i] = 0.f; }
#pragma unroll
    for (int i = 0; i < 2; i++) {
#pragma unroll
        for (int j = 0; j < 8; j++) {
            const int nc = wn * 64 + j * 8 + 2 * ctid;
            float y0 = acc[i][j][0] + bias_s[nc];
            float y1 = acc[i][j][1] + bias_s[nc + 1];
            float y2 = acc[i][j][2] + bias_s[nc];
            float y3 = acc[i][j][3] + bias_s[nc + 1];
            acc[i][j][0] = y0; acc[i][j][1] = y1; acc[i][j][2] = y2; acc[i][j][3] = y3;
            psum0[i] += y0 + y1;  psq0[i] += y0 * y0 + y1 * y1;
            psum1[i] += y2 + y3;  psq1[i] += y2 * y2 + y3 * y3;
        }
    }
#pragma unroll
    for (int i = 0; i < 2; i++) {
#pragma unroll
        for (int d = 1; d < 4; d <<= 1) {
            psum0[i] += __shfl_xor_sync(0xffffffffu, psum0[i], d);
            psq0[i]  += __shfl_xor_sync(0xffffffffu, psq0[i], d);
            psum1[i] += __shfl_xor_sync(0xffffffffu, psum1[i], d);
            psq1[i]  += __shfl_xor_sync(0xffffffffu, psq1[i], d);
        }
        if (ctid == 0) {
            const int r0 = wm * 32 + i * 16 + gid;
            atomicAdd(&red_s[r0], psum0[i]);
            atomicAdd(&red_s[TILE_M + r0], psq0[i]);
            atomicAdd(&red_s[r0 + 8], psum1[i]);
            atomicAdd(&red_s[TILE_M + r0 + 8], psq1[i]);
        }
    }
    __syncthreads();

    // ---- cluster exchange of per-row partials ----
    uint32_t myrank;
    asm("mov.u32 %0, %%cluster_ctarank;" : "=r"(myrank));
    const uint32_t peer = myrank ^ 1u;

    asm volatile("barrier.cluster.arrive.aligned;" ::: "memory");
    asm volatile("barrier.cluster.wait.aligned;" ::: "memory");

    if (tid < TILE_M) {
        const uint32_t lsum = sb + SM_RED + tid * 4;
        const uint32_t lsq  = lsum + TILE_M * 4;
        uint32_t rsum, rsq;
        asm("mapa.shared::cluster.u32 %0, %1, %2;" : "=r"(rsum) : "r"(lsum), "r"(peer));
        asm("mapa.shared::cluster.u32 %0, %1, %2;" : "=r"(rsq)  : "r"(lsq),  "r"(peer));
        float ps, pq;
        asm volatile("ld.shared::cluster.f32 %0, [%1];" : "=f"(ps) : "r"(rsum));
        asm volatile("ld.shared::cluster.f32 %0, [%1];" : "=f"(pq) : "r"(rsq));
        const float s  = red_s[tid] + ps;
        const float sq = red_s[TILE_M + tid] + pq;
        const float mean = s * (1.0f / 512.0f);
        const float var  = fmaxf(sq * (1.0f / 512.0f) - mean * mean, 0.f);
        mean_s[tid] = mean;
        rstd_s[tid] = rsqrtf(var + 1e-5f);
    }
    __syncthreads();
    asm volatile("barrier.cluster.arrive.aligned;" ::: "memory");

    // ---- normalize + SiLU chain + store ----
    float* obase = out + (size_t)(bm * TILE_M) * N_DIM + nbase;
#pragma unroll
    for (int i = 0; i < 2; i++) {
        const int r0 = wm * 32 + i * 16 + gid;
        const float m0 = mean_s[r0],     rs0 = rstd_s[r0];
        const float m1 = mean_s[r0 + 8], rs1 = rstd_s[r0 + 8];
#pragma unroll
        for (int j = 0; j < 8; j++) {
            const int nc = wn * 64 + j * 8 + 2 * ctid;
            const float gw0 = gnw_s[nc], gw1 = gnw_s[nc + 1];
            const float gb0 = gnb_s[nc], gb1 = gnb_s[nc + 1];
            const float w0  = mw_s[nc],  w1  = mw_s[nc + 1];
            float v[4];
            {
                float t0 = (acc[i][j][0] - m0) * rs0 * gw0 + gb0;
                float t1 = (acc[i][j][1] - m0) * rs0 * gw1 + gb1;
                float t2 = (acc[i][j][2] - m1) * rs1 * gw0 + gb0;
                float t3 = (acc[i][j][3] - m1) * rs1 * gw1 + gb1;
                float s0 = t0 / (1.f + __expf(-t0)) * w0;
                float s1 = t1 / (1.f + __expf(-t1)) * w1;
                float s2 = t2 / (1.f + __expf(-t2)) * w0;
                float s3 = t3 / (1.f + __expf(-t3)) * w1;
                v[0] = s0 / (1.f + __expf(-s0));
                v[1] = s1 / (1.f + __expf(-s1));
                v[2] = s2 / (1.f + __expf(-s2));
                v[3] = s3 / (1.f + __expf(-s3));
            }
            float2* p0 = (float2*)(obase + (size_t)r0 * N_DIM + nc);
            float2* p1 = (float2*)(obase + (size_t)(r0 + 8) * N_DIM + nc);
            *p0 = make_float2(v[0], v[1]);
            *p1 = make_float2(v[2], v[3]);
        }
    }

    asm volatile("barrier.cluster.wait.aligned;" ::: "memory");
}

extern "C" void kernel_launch(void* const* d_in, const int* in_sizes, int n_in,
                              void* d_out, int out_size)
{
    const float* x   = (const float*)d_in[0];
    const float* W   = (const float*)d_in[1];
    const float* b   = (const float*)d_in[2];
    const float* gnw = (const float*)d_in[3];
    const float* gnb = (const float*)d_in[4];
    const float* mw  = (const float*)d_in[5];
    float* out = (float*)d_out;

    convert_f32_to_f16<<<2048, 256>>>(x, W);

    cudaFuncSetAttribute(fused_gemm_gn_silu,
                         cudaFuncAttributeMaxDynamicSharedMemorySize, SMEM_TOTAL);
    fused_gemm_gn_silu<<<GRID, THREADS, SMEM_TOTAL>>>(b, gnw, gnb, mw, out);
}